// round 12
// baseline (speedup 1.0000x reference)
#include <cuda_runtime.h>
#include <cuda_bf16.h>
#include <cstdint>
#include <cstddef>

// ---------------------------------------------------------------------------
// Scratch (__device__ globals; no cudaMalloc allowed)
// ---------------------------------------------------------------------------
__device__ float g_c[64];
__device__ __align__(16) __nv_bfloat16 g_Mhi[64 * 1024];
__device__ __align__(16) __nv_bfloat16 g_Mlo[64 * 1024];
__device__ int g_cnt[9 * 32];   // ch*32: chunk counters (target 1024); 8*32: c (target 64)

#define CNT_C     (8 * 32)

// ---------------------------------------------------------------------------
// Kernel A: blocks [0,64): c[k] = b[k] + V2[k]·x2          (launched first)
//           blocks [64,8256): M[k,d] = V[k,d] + W[k,d,:]·x2 -> bf16 hi/lo
// Chunk-ordered: ch = (bid-64)>>10, so chunk counters complete in order.
// ---------------------------------------------------------------------------
__global__ __launch_bounds__(256) void wx2_kernel(const float* __restrict__ W,
                                                  const float* __restrict__ V,
                                                  const float* __restrict__ x2,
                                                  const float* __restrict__ b) {
    if (blockIdx.x < 64) {
        int k = blockIdx.x;
        if (threadIdx.x < 32) {
            int lane = threadIdx.x;
            const float4* v = reinterpret_cast<const float4*>(V + (size_t)k * 2048 + 1024);
            const float4* xx = reinterpret_cast<const float4*>(x2);
            float s = 0.0f;
#pragma unroll
            for (int i = 0; i < 8; i++) {
                float4 a = v[lane + i * 32];
                float4 c = xx[lane + i * 32];
                s += a.x * c.x + a.y * c.y + a.z * c.z + a.w * c.w;
            }
#pragma unroll
            for (int o = 16; o; o >>= 1) s += __shfl_xor_sync(0xFFFFFFFFu, s, o);
            if (lane == 0) {
                g_c[k] = s + b[k];
                __threadfence();
                atomicAdd(&g_cnt[CNT_C], 1);    // target 64
            }
        }
        return;
    }

    __shared__ float sx2[1024];
    {
        const float4* src = reinterpret_cast<const float4*>(x2);
        float4* dst = reinterpret_cast<float4*>(sx2);
        dst[threadIdx.x] = src[threadIdx.x];
    }
    __syncthreads();

    int bid = blockIdx.x - 64;
    int ch = bid >> 10;                 // 0..7  (slowest-varying: chunks finish in order)
    int rem = bid & 1023;
    int k = rem >> 4;                   // 0..63
    int oct = rem & 15;                 // 0..15
    int w = threadIdx.x >> 5;           // warp 0..7
    int lane = threadIdx.x & 31;
    int d = ch * 128 + oct * 8 + w;
    int pair = k * 1024 + d;

    const float4* wp = reinterpret_cast<const float4*>(W + (size_t)pair * 1024);
    const float4* xx = reinterpret_cast<const float4*>(sx2);

    float s = 0.0f;
#pragma unroll
    for (int i = 0; i < 8; i++) {
        float4 wv = __ldcs(&wp[lane + i * 32]);  // streaming: W touched exactly once
        float4 xv = xx[lane + i * 32];
        s += wv.x * xv.x + wv.y * xv.y + wv.z * xv.z + wv.w * xv.w;
    }
#pragma unroll
    for (int o = 16; o; o >>= 1) s += __shfl_xor_sync(0xFFFFFFFFu, s, o);

    if (lane == 0) {
        float m = s + V[(size_t)k * 2048 + d];
        __nv_bfloat16 hi = __float2bfloat16_rn(m);
        __nv_bfloat16 lo = __float2bfloat16_rn(m - __bfloat162float(hi));
        g_Mhi[pair] = hi;
        g_Mlo[pair] = lo;
        __threadfence();                 // writer-side fence before block signal
    }
    __syncthreads();
    if (threadIdx.x == 0) atomicAdd(&g_cnt[ch * 32], 1);   // target 1024 per chunk
}

// ---------------------------------------------------------------------------
// Kernel B (concurrent stream): split-bf16 HMMA GEMM + fused relu/U epilogue,
// consuming M chunk-by-chunk behind wx2 via counter waits.
// Grid 128 CTAs (BM=64), 256 thr; ldmatrix.x4 fragments; B via cp.async.
// ---------------------------------------------------------------------------
#define CHUNK     128
#define LDA       136
#define A_HI      0
#define A_LO      17408
#define B_HI      34816
#define B_LO      52224
#define STAGE_BYTES 69632
#define RED_OFF   (2 * STAGE_BYTES)
#define SMEM_TOTAL (RED_OFF + 512)

__device__ __forceinline__ uint32_t smem_u32(const void* p) {
    return (uint32_t)__cvta_generic_to_shared(p);
}

__device__ __forceinline__ int ld_acquire(const int* p) {
    int v;
    asm volatile("ld.acquire.gpu.b32 %0, [%1];" : "=r"(v) : "l"(p) : "memory");
    return v;
}

// Poll by lane 0 of warp 0 only; everyone else parks at __syncthreads().
__device__ __forceinline__ void wait_cnt(const int* c, int target) {
    if ((threadIdx.x & 31) == 0) {
        while (ld_acquire(c) < target) __nanosleep(128);
    }
    __syncwarp();
}

#define CP_ASYNC16(dst_u32, src_ptr) \
    asm volatile("cp.async.cg.shared.global [%0], [%1], 16;" :: "r"(dst_u32), "l"(src_ptr))
#define CP_COMMIT() asm volatile("cp.async.commit_group;" ::: "memory")
#define CP_WAIT0()  asm volatile("cp.async.wait_group 0;" ::: "memory")

#define LDSM4(r0, r1, r2, r3, addr) \
    asm volatile("ldmatrix.sync.aligned.m8n8.x4.shared.b16 {%0,%1,%2,%3}, [%4];" \
                 : "=r"(r0), "=r"(r1), "=r"(r2), "=r"(r3) : "r"(addr))

__device__ __forceinline__ uint32_t pack_bf16x2(__nv_bfloat16 a, __nv_bfloat16 b) {
    __nv_bfloat162 t; t.x = a; t.y = b;
    return *reinterpret_cast<uint32_t*>(&t);
}

__device__ __forceinline__ void split_pair(float f0, float f1, uint32_t& h, uint32_t& l) {
    __nv_bfloat16 h0 = __float2bfloat16_rn(f0);
    __nv_bfloat16 h1 = __float2bfloat16_rn(f1);
    h = pack_bf16x2(h0, h1);
    l = pack_bf16x2(__float2bfloat16_rn(f0 - __bfloat162float(h0)),
                    __float2bfloat16_rn(f1 - __bfloat162float(h1)));
}

__device__ __forceinline__ void mma16816(float d[4], const uint32_t a[4],
                                         uint32_t b0, uint32_t b1) {
    asm volatile(
        "mma.sync.aligned.m16n8k16.row.col.f32.bf16.bf16.f32 "
        "{%0,%1,%2,%3}, {%4,%5,%6,%7}, {%8,%9}, {%0,%1,%2,%3};"
        : "+f"(d[0]), "+f"(d[1]), "+f"(d[2]), "+f"(d[3])
        : "r"(a[0]), "r"(a[1]), "r"(a[2]), "r"(a[3]), "r"(b0), "r"(b1));
}

__device__ __forceinline__ void ldg_a(const float* __restrict__ x1, int row0, int ch,
                                      int tid, float4 pa[8]) {
#pragma unroll
    for (int t = 0; t < 8; t++) {
        int g = tid + t * 256;
        int r = g >> 5;
        int c4 = (g & 31) * 4;
        pa[t] = *reinterpret_cast<const float4*>(x1 + (size_t)(row0 + r) * 1024 + ch * CHUNK + c4);
    }
}

__device__ __forceinline__ void cpasync_b(char* stage, int ch, int tid) {
    uint32_t sh = smem_u32(stage + B_HI);
    uint32_t sl = smem_u32(stage + B_LO);
#pragma unroll
    for (int t = 0; t < 4; t++) {
        int g = tid + t * 256;
        int n = g >> 4;
        int u = g & 15;
        uint32_t doff = (uint32_t)(n * (LDA * 2) + u * 16);
        const __nv_bfloat16* srch = g_Mhi + (size_t)n * 1024 + ch * CHUNK + u * 8;
        const __nv_bfloat16* srcl = g_Mlo + (size_t)n * 1024 + ch * CHUNK + u * 8;
        CP_ASYNC16(sh + doff, srch);
        CP_ASYNC16(sl + doff, srcl);
    }
}

__device__ __forceinline__ void sts_a(char* stage, int tid, const float4 pa[8]) {
#pragma unroll
    for (int t = 0; t < 8; t++) {
        int g = tid + t * 256;
        int r = g >> 5;
        int c4 = (g & 31) * 4;
        uint32_t h0, l0, h1, l1;
        split_pair(pa[t].x, pa[t].y, h0, l0);
        split_pair(pa[t].z, pa[t].w, h1, l1);
        int off = (r * LDA + c4) * 2;
        *reinterpret_cast<uint2*>(stage + A_HI + off) = make_uint2(h0, h1);
        *reinterpret_cast<uint2*>(stage + A_LO + off) = make_uint2(l0, l1);
    }
}

__device__ __forceinline__ void compute_chunk(uint32_t st, int m0, int nb,
                                              int lane, float d[4][4]) {
    int arow = m0 + (lane & 15);
    int acol = (lane >> 4) << 3;
    int nrow = (lane & 7) + ((lane & 16) >> 1);
    int bcol = lane & 8;
    uint32_t ah = st + A_HI + (uint32_t)(arow * LDA + acol) * 2;
    uint32_t al = st + A_LO + (uint32_t)(arow * LDA + acol) * 2;
    uint32_t ph = st + B_HI + (uint32_t)((nb + nrow) * LDA + bcol) * 2;
    uint32_t pl = st + B_LO + (uint32_t)((nb + nrow) * LDA + bcol) * 2;
    const uint32_t nstep = 16u * LDA * 2u;

#pragma unroll
    for (int ks = 0; ks < CHUNK / 16; ks++) {
        uint32_t koff = (uint32_t)ks * 32;
        uint32_t A[4], C[4];
        uint32_t p0, p1, p2, p3, q0, q1, q2, q3;
        uint32_t r0, r1, r2, r3, s0, s1, s2, s3;
        LDSM4(A[0], A[1], A[2], A[3], ah + koff);
        LDSM4(C[0], C[1], C[2], C[3], al + koff);
        LDSM4(p0, p1, p2, p3, ph + koff);
        LDSM4(q0, q1, q2, q3, ph + nstep + koff);
        LDSM4(r0, r1, r2, r3, pl + koff);
        LDSM4(s0, s1, s2, s3, pl + nstep + koff);
        mma16816(d[0], A, p0, p1);
        mma16816(d[1], A, p2, p3);
        mma16816(d[2], A, q0, q1);
        mma16816(d[3], A, q2, q3);
        mma16816(d[0], A, r0, r1);
        mma16816(d[1], A, r2, r3);
        mma16816(d[2], A, s0, s1);
        mma16816(d[3], A, s2, s3);
        mma16816(d[0], C, p0, p1);
        mma16816(d[1], C, p2, p3);
        mma16816(d[2], C, q0, q1);
        mma16816(d[3], C, q2, q3);
    }
}

__global__ __launch_bounds__(256, 1) void gemm_mma(const float* __restrict__ x1,
                                                   const float* __restrict__ U,
                                                   float* __restrict__ out) {
    extern __shared__ char smem[];
    int tid = threadIdx.x, lane = tid & 31, wid = tid >> 5;
    int wr = wid & 3, wc = wid >> 2;
    int m0 = wr * 16, nb = wc * 32;
    int row0 = blockIdx.x * 64;
    float* red = reinterpret_cast<float*>(smem + RED_OFF);

    float d[4][4] = {};
    float4 pa[8];

    ldg_a(x1, row0, 0, tid, pa);                 // x1 LDGs fly while we wait
    if (wid == 0) wait_cnt(&g_cnt[0], 1024);
    __syncthreads();
    cpasync_b(smem, 0, tid);
    CP_COMMIT();
    sts_a(smem, tid, pa);
    CP_WAIT0();
    __syncthreads();

    for (int ch = 0; ch < 8; ch++) {
        char* cur = smem + (ch & 1) * STAGE_BYTES;
        char* nxt = smem + ((ch + 1) & 1) * STAGE_BYTES;
        if (ch < 7) {
            ldg_a(x1, row0, ch + 1, tid, pa);
            if (wid == 0) wait_cnt(&g_cnt[(ch + 1) * 32], 1024);
            __syncthreads();
            cpasync_b(nxt, ch + 1, tid);
            CP_COMMIT();
        }
        compute_chunk(smem_u32(cur), m0, nb, lane, d);
        if (ch < 7) {
            sts_a(nxt, tid, pa);
            CP_WAIT0();
            __syncthreads();
        }
    }

    // fused epilogue: relu(D + c)*U, row-reduce over 64 cols -> out (N,1)
    if (wid == 0) wait_cnt(&g_cnt[CNT_C], 64);
    __syncthreads();
    int g = lane >> 2, tg2 = (lane & 3) * 2;
    float accA = 0.0f, accB = 0.0f;
#pragma unroll
    for (int j = 0; j < 4; j++) {
        int col = nb + j * 8 + tg2;
        float c0 = g_c[col], c1 = g_c[col + 1];
        float u0 = U[col], u1 = U[col + 1];
        accA += fmaxf(d[j][0] + c0, 0.0f) * u0 + fmaxf(d[j][1] + c1, 0.0f) * u1;
        accB += fmaxf(d[j][2] + c0, 0.0f) * u0 + fmaxf(d[j][3] + c1, 0.0f) * u1;
    }
    accA += __shfl_xor_sync(0xFFFFFFFFu, accA, 1);
    accA += __shfl_xor_sync(0xFFFFFFFFu, accA, 2);
    accB += __shfl_xor_sync(0xFFFFFFFFu, accB, 1);
    accB += __shfl_xor_sync(0xFFFFFFFFu, accB, 2);
    if ((lane & 3) == 0) {
        red[wc * 64 + m0 + g] = accA;
        red[wc * 64 + m0 + 8 + g] = accB;
    }
    __syncthreads();
    if (tid < 64) out[row0 + tid] = red[tid] + red[64 + tid];
}

// ---------------------------------------------------------------------------
// Fork-join across two streams (graph-capturable; no allocation).
// ---------------------------------------------------------------------------
extern "C" void kernel_launch(void* const* d_in, const int* in_sizes, int n_in,
                              void* d_out, int out_size) {
    const float* x1 = (const float*)d_in[0];  // (8192, 1024)
    const float* x2 = (const float*)d_in[1];  // (1, 1024)
    const float* V  = (const float*)d_in[2];  // (64, 2048)
    const float* W  = (const float*)d_in[3];  // (64, 1024, 1024)
    const float* b  = (const float*)d_in[4];  // (64,)
    const float* U  = (const float*)d_in[5];  // (64, 1)
    float* out = (float*)d_out;               // (8192, 1)

    static cudaStream_t s2 = nullptr;
    static cudaEvent_t ev_fork = nullptr, ev_join = nullptr;
    if (s2 == nullptr) {   // one-time resource creation (first call is outside capture)
        cudaStreamCreateWithFlags(&s2, cudaStreamNonBlocking);
        cudaEventCreateWithFlags(&ev_fork, cudaEventDisableTiming);
        cudaEventCreateWithFlags(&ev_join, cudaEventDisableTiming);
        cudaFuncSetAttribute(gemm_mma, cudaFuncAttributeMaxDynamicSharedMemorySize, SMEM_TOTAL);
    }

    void* cnt_addr = nullptr;
    cudaGetSymbolAddress(&cnt_addr, g_cnt);
    cudaMemsetAsync(cnt_addr, 0, sizeof(int) * 9 * 32, 0);

    cudaEventRecord(ev_fork, 0);
    cudaStreamWaitEvent(s2, ev_fork, 0);

    wx2_kernel<<<8256, 256, 0, 0>>>(W, V, x2, b);        // full-occupancy HBM stream
    gemm_mma<<<128, 256, SMEM_TOTAL, s2>>>(x1, U, out);  // concurrent chunk consumer

    cudaEventRecord(ev_join, s2);
    cudaStreamWaitEvent(0, ev_join, 0);
}

// round 13
// speedup vs baseline: 1.1298x; 1.1298x over previous
#include <cuda_runtime.h>
#include <cuda_bf16.h>
#include <cstdint>
#include <cstddef>

// ---------------------------------------------------------------------------
// Scratch (__device__ globals; no cudaMalloc allowed)
// ---------------------------------------------------------------------------
__device__ float g_c[64];
__device__ __align__(16) __nv_bfloat16 g_Mhi[64 * 1024];
__device__ __align__(16) __nv_bfloat16 g_Mlo[64 * 1024];

// ---------------------------------------------------------------------------
// Kernel A (fused): blocks [0,8192): M[k,d] = V[k,d] + sum_e W[k,d,e]*x2[e]
//                   blocks [8192,8256): c[k] = b[k] + V2[k]·x2
// One warp per (k,d) pair; streams 256 MB of W once (HBM-bound, ~82% DRAM).
// ---------------------------------------------------------------------------
__global__ __launch_bounds__(256) void wx2_kernel(const float* __restrict__ W,
                                                  const float* __restrict__ V,
                                                  const float* __restrict__ x2,
                                                  const float* __restrict__ b) {
    if (blockIdx.x >= 8192) {
        int k = blockIdx.x - 8192;
        if (threadIdx.x < 32) {
            int lane = threadIdx.x;
            const float4* v = reinterpret_cast<const float4*>(V + (size_t)k * 2048 + 1024);
            const float4* xx = reinterpret_cast<const float4*>(x2);
            float s = 0.0f;
#pragma unroll
            for (int i = 0; i < 8; i++) {
                float4 a = v[lane + i * 32];
                float4 c = xx[lane + i * 32];
                s += a.x * c.x + a.y * c.y + a.z * c.z + a.w * c.w;
            }
#pragma unroll
            for (int o = 16; o; o >>= 1) s += __shfl_xor_sync(0xFFFFFFFFu, s, o);
            if (lane == 0) g_c[k] = s + b[k];
        }
        return;
    }

    __shared__ float sx2[1024];
    {
        const float4* src = reinterpret_cast<const float4*>(x2);
        float4* dst = reinterpret_cast<float4*>(sx2);
        dst[threadIdx.x] = src[threadIdx.x];
    }
    __syncthreads();

    int pair = blockIdx.x * 8 + (threadIdx.x >> 5);
    int lane = threadIdx.x & 31;
    int k = pair >> 10;
    int d = pair & 1023;

    const float4* w = reinterpret_cast<const float4*>(W + (size_t)pair * 1024);
    const float4* xx = reinterpret_cast<const float4*>(sx2);

    float s = 0.0f;
#pragma unroll
    for (int i = 0; i < 8; i++) {
        float4 wv = __ldcs(&w[lane + i * 32]);   // streaming: W touched exactly once
        float4 xv = xx[lane + i * 32];
        s += wv.x * xv.x + wv.y * xv.y + wv.z * xv.z + wv.w * xv.w;
    }
#pragma unroll
    for (int o = 16; o; o >>= 1) s += __shfl_xor_sync(0xFFFFFFFFu, s, o);

    if (lane == 0) {
        float m = s + V[(size_t)k * 2048 + d];
        __nv_bfloat16 hi = __float2bfloat16_rn(m);
        __nv_bfloat16 lo = __float2bfloat16_rn(m - __bfloat162float(hi));
        g_Mhi[pair] = hi;
        g_Mlo[pair] = lo;
    }
}

// ---------------------------------------------------------------------------
// Kernel B: split-bf16 HMMA GEMM + fused relu/U epilogue.
// out[n] = sum_k relu((x1 @ M^T)[n,k] + c[k]) * U[k]
// Grid 128 CTAs (BM=64), 512 thr (16 warps as 4x4) -> 4 warps/SMSP for
// latency hiding. Warp tile 16m x 16n. ldmatrix.x4 fragments; B via cp.async.
// ---------------------------------------------------------------------------
#define CHUNK     128
#define LDA       136
#define A_HI      0
#define A_LO      17408
#define B_HI      34816
#define B_LO      52224
#define STAGE_BYTES 69632
#define RED_OFF   (2 * STAGE_BYTES)      // 139264
#define SMEM_TOTAL (RED_OFF + 1024)      // 140288

__device__ __forceinline__ uint32_t smem_u32(const void* p) {
    return (uint32_t)__cvta_generic_to_shared(p);
}

#define CP_ASYNC16(dst_u32, src_ptr) \
    asm volatile("cp.async.cg.shared.global [%0], [%1], 16;" :: "r"(dst_u32), "l"(src_ptr))
#define CP_COMMIT() asm volatile("cp.async.commit_group;" ::: "memory")
#define CP_WAIT0()  asm volatile("cp.async.wait_group 0;" ::: "memory")

#define LDSM4(r0, r1, r2, r3, addr) \
    asm volatile("ldmatrix.sync.aligned.m8n8.x4.shared.b16 {%0,%1,%2,%3}, [%4];" \
                 : "=r"(r0), "=r"(r1), "=r"(r2), "=r"(r3) : "r"(addr))

__device__ __forceinline__ uint32_t pack_bf16x2(__nv_bfloat16 a, __nv_bfloat16 b) {
    __nv_bfloat162 t; t.x = a; t.y = b;
    return *reinterpret_cast<uint32_t*>(&t);
}

__device__ __forceinline__ void split_pair(float f0, float f1, uint32_t& h, uint32_t& l) {
    __nv_bfloat16 h0 = __float2bfloat16_rn(f0);
    __nv_bfloat16 h1 = __float2bfloat16_rn(f1);
    h = pack_bf16x2(h0, h1);
    l = pack_bf16x2(__float2bfloat16_rn(f0 - __bfloat162float(h0)),
                    __float2bfloat16_rn(f1 - __bfloat162float(h1)));
}

__device__ __forceinline__ void mma16816(float d[4], const uint32_t a[4],
                                         uint32_t b0, uint32_t b1) {
    asm volatile(
        "mma.sync.aligned.m16n8k16.row.col.f32.bf16.bf16.f32 "
        "{%0,%1,%2,%3}, {%4,%5,%6,%7}, {%8,%9}, {%0,%1,%2,%3};"
        : "+f"(d[0]), "+f"(d[1]), "+f"(d[2]), "+f"(d[3])
        : "r"(a[0]), "r"(a[1]), "r"(a[2]), "r"(a[3]), "r"(b0), "r"(b1));
}

// A chunk: 64 rows x 128 fp32 = 2048 float4; 4 per thread (512 thr)
__device__ __forceinline__ void ldg_a(const float* __restrict__ x1, int row0, int ch,
                                      int tid, float4 pa[4]) {
#pragma unroll
    for (int t = 0; t < 4; t++) {
        int g = tid + t * 512;              // 0..2047
        int r = g >> 5;                     // row 0..63
        int c4 = (g & 31) * 4;              // col 0..124
        pa[t] = *reinterpret_cast<const float4*>(x1 + (size_t)(row0 + r) * 1024 + ch * CHUNK + c4);
    }
}

// B chunk via cp.async: hi + lo, 64 rows x 16 x 16B units each; 4 cp/thread
__device__ __forceinline__ void cpasync_b(char* stage, int ch, int tid) {
    uint32_t sh = smem_u32(stage + B_HI);
    uint32_t sl = smem_u32(stage + B_LO);
#pragma unroll
    for (int t = 0; t < 2; t++) {
        int g = tid + t * 512;              // 0..1023
        int n = g >> 4;                     // k_out 0..63
        int u = g & 15;                     // 16B unit 0..15
        uint32_t doff = (uint32_t)(n * (LDA * 2) + u * 16);
        const __nv_bfloat16* srch = g_Mhi + (size_t)n * 1024 + ch * CHUNK + u * 8;
        const __nv_bfloat16* srcl = g_Mlo + (size_t)n * 1024 + ch * CHUNK + u * 8;
        CP_ASYNC16(sh + doff, srch);
        CP_ASYNC16(sl + doff, srcl);
    }
}

__device__ __forceinline__ void sts_a(char* stage, int tid, const float4 pa[4]) {
#pragma unroll
    for (int t = 0; t < 4; t++) {
        int g = tid + t * 512;
        int r = g >> 5;
        int c4 = (g & 31) * 4;
        uint32_t h0, l0, h1, l1;
        split_pair(pa[t].x, pa[t].y, h0, l0);
        split_pair(pa[t].z, pa[t].w, h1, l1);
        int off = (r * LDA + c4) * 2;
        *reinterpret_cast<uint2*>(stage + A_HI + off) = make_uint2(h0, h1);
        *reinterpret_cast<uint2*>(stage + A_LO + off) = make_uint2(l0, l1);
    }
}

// Warp tile 16m x 16n; 4 LDSM.x4 + 6 MMA per ks; 2 accumulator chains.
__device__ __forceinline__ void compute_chunk(uint32_t st, int m0, int nb,
                                              int lane, float d[2][4]) {
    int arow = m0 + (lane & 15);
    int acol = (lane >> 4) << 3;                 // 0 or 8
    int nrow = (lane & 7) + ((lane & 16) >> 1);  // 0..15
    int bcol = lane & 8;                         // 0 or 8
    uint32_t ah = st + A_HI + (uint32_t)(arow * LDA + acol) * 2;
    uint32_t al = st + A_LO + (uint32_t)(arow * LDA + acol) * 2;
    uint32_t ph = st + B_HI + (uint32_t)((nb + nrow) * LDA + bcol) * 2;
    uint32_t pl = st + B_LO + (uint32_t)((nb + nrow) * LDA + bcol) * 2;

#pragma unroll
    for (int ks = 0; ks < CHUNK / 16; ks++) {
        uint32_t koff = (uint32_t)ks * 32;
        uint32_t A[4], C[4];
        uint32_t p0, p1, p2, p3;                 // B hi: n[0:8)k0, n[0:8)k8, n[8:16)k0, n[8:16)k8
        uint32_t r0, r1, r2, r3;                 // B lo
        LDSM4(A[0], A[1], A[2], A[3], ah + koff);
        LDSM4(C[0], C[1], C[2], C[3], al + koff);
        LDSM4(p0, p1, p2, p3, ph + koff);
        LDSM4(r0, r1, r2, r3, pl + koff);
        // 2 accumulator chains, 3 deep (hh, hl, lh)
        mma16816(d[0], A, p0, p1);
        mma16816(d[1], A, p2, p3);
        mma16816(d[0], A, r0, r1);
        mma16816(d[1], A, r2, r3);
        mma16816(d[0], C, p0, p1);
        mma16816(d[1], C, p2, p3);
    }
}

__global__ __launch_bounds__(512, 1) void gemm_mma(const float* __restrict__ x1,
                                                   const float* __restrict__ U,
                                                   float* __restrict__ out) {
    extern __shared__ char smem[];
    int tid = threadIdx.x, lane = tid & 31, wid = tid >> 5;
    int wr = wid & 3, wc = wid >> 2;             // 4x4 warp grid
    int m0 = wr * 16, nb = wc * 16;
    int row0 = blockIdx.x * 64;
    float* red = reinterpret_cast<float*>(smem + RED_OFF);

    float d[2][4] = {};
    float4 pa[4];

    ldg_a(x1, row0, 0, tid, pa);
    cpasync_b(smem, 0, tid);
    CP_COMMIT();
    sts_a(smem, tid, pa);
    CP_WAIT0();
    __syncthreads();

    for (int ch = 0; ch < 8; ch++) {
        char* cur = smem + (ch & 1) * STAGE_BYTES;
        char* nxt = smem + ((ch + 1) & 1) * STAGE_BYTES;
        if (ch < 7) {
            ldg_a(x1, row0, ch + 1, tid, pa);     // x1 LDGs fly during compute
            cpasync_b(nxt, ch + 1, tid);
            CP_COMMIT();
        }
        compute_chunk(smem_u32(cur), m0, nb, lane, d);
        if (ch < 7) {
            sts_a(nxt, tid, pa);
            CP_WAIT0();
            __syncthreads();
        }
    }

    // fused epilogue: relu(D + c)*U over this warp's 16 cols, reduce -> out
    int g = lane >> 2, tg2 = (lane & 3) * 2;
    float accA = 0.0f, accB = 0.0f;
#pragma unroll
    for (int j = 0; j < 2; j++) {
        int col = nb + j * 8 + tg2;
        float c0 = g_c[col], c1 = g_c[col + 1];
        float u0 = U[col], u1 = U[col + 1];
        accA += fmaxf(d[j][0] + c0, 0.0f) * u0 + fmaxf(d[j][1] + c1, 0.0f) * u1;
        accB += fmaxf(d[j][2] + c0, 0.0f) * u0 + fmaxf(d[j][3] + c1, 0.0f) * u1;
    }
    accA += __shfl_xor_sync(0xFFFFFFFFu, accA, 1);
    accA += __shfl_xor_sync(0xFFFFFFFFu, accA, 2);
    accB += __shfl_xor_sync(0xFFFFFFFFu, accB, 1);
    accB += __shfl_xor_sync(0xFFFFFFFFu, accB, 2);
    if ((lane & 3) == 0) {
        red[wc * 64 + m0 + g] = accA;
        red[wc * 64 + m0 + 8 + g] = accB;
    }
    __syncthreads();
    if (tid < 64) {
        out[row0 + tid] = (red[tid] + red[64 + tid]) + (red[128 + tid] + red[192 + tid]);
    }
}

// ---------------------------------------------------------------------------
extern "C" void kernel_launch(void* const* d_in, const int* in_sizes, int n_in,
                              void* d_out, int out_size) {
    const float* x1 = (const float*)d_in[0];  // (8192, 1024)
    const float* x2 = (const float*)d_in[1];  // (1, 1024)
    const float* V  = (const float*)d_in[2];  // (64, 2048)
    const float* W  = (const float*)d_in[3];  // (64, 1024, 1024)
    const float* b  = (const float*)d_in[4];  // (64,)
    const float* U  = (const float*)d_in[5];  // (64, 1)
    float* out = (float*)d_out;               // (8192, 1)

    cudaFuncSetAttribute(gemm_mma, cudaFuncAttributeMaxDynamicSharedMemorySize, SMEM_TOTAL);

    wx2_kernel<<<8192 + 64, 256>>>(W, V, x2, b);     // HBM-bound + fused c blocks
    gemm_mma<<<128, 512, SMEM_TOTAL>>>(x1, U, out);  // 16-warp HMMA GEMM + epilogue
}